// round 3
// baseline (speedup 1.0000x reference)
#include <cuda_runtime.h>
#include <cstdint>
#include <cstddef>

#define TT 512
#define BB 256
#define HH 128
#define G3 384
#define MM (BB * TT)

// Scratch (device globals — no allocations allowed)
__device__ float g_gx[(size_t)MM * G3];     // [B*T, 384] input-side gates (reused per layer)
__device__ float g_h1[(size_t)MM * HH];     // [B*T, 128] layer-1 outputs
__device__ float g_hlast[BB * HH];          // [B, 128] final hidden of layer 2

// ---------------- packed f32x2 helpers ----------------
__device__ __forceinline__ unsigned long long pack2(float x, float y) {
    unsigned long long r;
    asm("mov.b64 %0, {%1, %2};" : "=l"(r) : "f"(x), "f"(y));
    return r;
}
__device__ __forceinline__ void unpack2(unsigned long long v, float& x, float& y) {
    asm("mov.b64 {%0, %1}, %2;" : "=f"(x), "=f"(y) : "l"(v));
}
__device__ __forceinline__ void fma2(unsigned long long& acc, unsigned long long a,
                                     unsigned long long b) {
    asm("fma.rn.f32x2 %0, %1, %2, %0;" : "+l"(acc) : "l"(a), "l"(b));
}

__device__ __forceinline__ float sigmoid_f(float x) {
    // 1/(1+e^-x); handles +-inf via rcp(inf)=0
    return __fdividef(1.f, 1.f + __expf(-x));
}
__device__ __forceinline__ float tanh_f(float x) {
    // 1 - 2/(1+e^{2x}); saturates correctly at +-1
    return 1.f - __fdividef(2.f, 1.f + __expf(2.f * x));
}

// ---------------- gx GEMM: out[m,n] = sum_k A[m,k]*W[n,k] + bias[n] ----------------
// A is either gathered embedding rows (GATHER) or a contiguous [M,128] buffer.
template <bool GATHER>
__global__ __launch_bounds__(256) void gx_kernel(
    const int* __restrict__ xtok,   // [M] tokens (GATHER only)
    const float* __restrict__ emb,  // [V,128]   (GATHER only)
    const float* __restrict__ Ain,  // [M,128]   (!GATHER)
    const float* __restrict__ W,    // [384,128] layer slice
    const float* __restrict__ bias, // [384] layer slice
    float* __restrict__ outp)       // [M,384]
{
    __shared__ float As[64][64];   // [m][k] chunk
    __shared__ float Bs[64][65];   // [n][k] chunk, +1 pad kills 16-way conflicts

    const int tid = threadIdx.x;
    const int tx = tid & 15;        // n-tile lane
    const int ty = tid >> 4;        // m-tile lane
    const int m0g = blockIdx.x * 64;
    const int n0g = blockIdx.y * 64;

    float c[4][4] = {};

    for (int kc = 0; kc < HH; kc += 64) {
        // fill A (coalesced float4 along k, direct copy)
#pragma unroll
        for (int p = 0; p < 4; p++) {
            int m = p * 16 + ty;
            const float* arow;
            if (GATHER) {
                int tokv = __ldg(xtok + m0g + m);
                arow = emb + (size_t)tokv * HH;
            } else {
                arow = Ain + (size_t)(m0g + m) * HH;
            }
            float4 v = *reinterpret_cast<const float4*>(arow + kc + tx * 4);
            *reinterpret_cast<float4*>(&As[m][tx * 4]) = v;
        }
        // fill B
#pragma unroll
        for (int p = 0; p < 4; p++) {
            int n = p * 16 + ty;
            float4 v = *reinterpret_cast<const float4*>(W + (size_t)(n0g + n) * HH + kc + tx * 4);
            Bs[n][tx * 4 + 0] = v.x;
            Bs[n][tx * 4 + 1] = v.y;
            Bs[n][tx * 4 + 2] = v.z;
            Bs[n][tx * 4 + 3] = v.w;
        }
        __syncthreads();
#pragma unroll
        for (int k = 0; k < 64; k++) {
            float a0 = As[ty * 4 + 0][k];
            float a1 = As[ty * 4 + 1][k];
            float a2 = As[ty * 4 + 2][k];
            float a3 = As[ty * 4 + 3][k];
            float b0 = Bs[tx * 4 + 0][k];
            float b1 = Bs[tx * 4 + 1][k];
            float b2 = Bs[tx * 4 + 2][k];
            float b3 = Bs[tx * 4 + 3][k];
            c[0][0] += a0 * b0; c[0][1] += a0 * b1; c[0][2] += a0 * b2; c[0][3] += a0 * b3;
            c[1][0] += a1 * b0; c[1][1] += a1 * b1; c[1][2] += a1 * b2; c[1][3] += a1 * b3;
            c[2][0] += a2 * b0; c[2][1] += a2 * b1; c[2][2] += a2 * b2; c[2][3] += a2 * b3;
            c[3][0] += a3 * b0; c[3][1] += a3 * b1; c[3][2] += a3 * b2; c[3][3] += a3 * b3;
        }
        __syncthreads();
    }

    float4 bv = *reinterpret_cast<const float4*>(bias + n0g + tx * 4);
#pragma unroll
    for (int i = 0; i < 4; i++) {
        int m = m0g + ty * 4 + i;
        float4 o;
        o.x = c[i][0] + bv.x;
        o.y = c[i][1] + bv.y;
        o.z = c[i][2] + bv.z;
        o.w = c[i][3] + bv.w;
        *reinterpret_cast<float4*>(outp + (size_t)m * G3 + n0g + tx * 4) = o;
    }
}

// ---------------- GRU recurrence: 2 samples per CTA, 384 threads ----------------
// Thread g owns gate row g: W_hh[g,:] in 64 packed f32x2 registers.
// h (both samples, k-paired) lives in smem as double2[64]:
//   float layout: [4*(j>>1) + 2*s + (j&1)]  (s=sample, j=hidden idx)
__global__ __launch_bounds__(384, 1) void gru_rec_kernel(
    const float* __restrict__ gx,    // [B,T,384]
    const float* __restrict__ Whh,   // [384,128] layer slice
    const float* __restrict__ bhh,   // [384] layer slice
    float* __restrict__ out_all,     // [B,T,128] or nullptr
    float* __restrict__ out_last)    // [B,128]   or nullptr
{
    __shared__ double2 sh_h[64];       // packed h for both samples
    __shared__ float sm_z[2][HH];
    __shared__ float2 sm_n[2][HH];     // (xn, hn_dot+bhh)

    const int g = threadIdx.x;
    const int s0 = blockIdx.x * 2;
    const int s1 = s0 + 1;

    // Load this thread's W_hh row, packed over k-pairs
    unsigned long long wp[64];
    const float2* wrow = reinterpret_cast<const float2*>(Whh + (size_t)g * HH);
#pragma unroll
    for (int kp = 0; kp < 64; kp++) {
        float2 w = wrow[kp];
        wp[kp] = pack2(w.x, w.y);
    }
    const float bh = bhh[g];

    if (g < 256) reinterpret_cast<float*>(sh_h)[g] = 0.f;  // h0 = 0
    float hprev0 = 0.f, hprev1 = 0.f;

    const float* gp0 = gx + (size_t)s0 * TT * G3 + g;
    const float* gp1 = gx + (size_t)s1 * TT * G3 + g;
    float cur0 = gp0[0];
    float cur1 = gp1[0];

    __syncthreads();

    for (int t = 0; t < TT; t++) {
        // prefetch next step's gx while the dot product runs
        float nxt0 = 0.f, nxt1 = 0.f;
        if (t + 1 < TT) {
            nxt0 = gp0[(size_t)(t + 1) * G3];
            nxt1 = gp1[(size_t)(t + 1) * G3];
        }

        // gh = W_hh[g,:] . h  (both samples, packed f32x2)
        unsigned long long acc0 = pack2(0.f, 0.f);
        unsigned long long acc1 = pack2(0.f, 0.f);
#pragma unroll
        for (int kp = 0; kp < 64; kp++) {
            double2 hv = sh_h[kp];
            fma2(acc0, wp[kp], (unsigned long long)__double_as_longlong(hv.x));
            fma2(acc1, wp[kp], (unsigned long long)__double_as_longlong(hv.y));
        }
        float lo, hi;
        unpack2(acc0, lo, hi);
        float d0 = lo + hi + bh;
        unpack2(acc1, lo, hi);
        float d1 = lo + hi + bh;

        float r0 = 0.f, r1 = 0.f;
        if (g < HH) {                       // r gates (warps 0-3): keep local
            r0 = sigmoid_f(cur0 + d0);
            r1 = sigmoid_f(cur1 + d1);
        } else if (g < 2 * HH) {            // z gates (warps 4-7)
            int j = g - HH;
            sm_z[0][j] = sigmoid_f(cur0 + d0);
            sm_z[1][j] = sigmoid_f(cur1 + d1);
        } else {                            // n gates (warps 8-11): publish (xn, hn)
            int j = g - 2 * HH;
            sm_n[0][j] = make_float2(cur0, d0);
            sm_n[1][j] = make_float2(cur1, d1);
        }
        __syncthreads();

        if (g < HH) {
            int j = g;
            float2 nh0 = sm_n[0][j];
            float z0 = sm_z[0][j];
            float n0 = tanh_f(nh0.x + r0 * nh0.y);
            float h0 = (1.f - z0) * n0 + z0 * hprev0;

            float2 nh1 = sm_n[1][j];
            float z1 = sm_z[1][j];
            float n1 = tanh_f(nh1.x + r1 * nh1.y);
            float h1v = (1.f - z1) * n1 + z1 * hprev1;

            hprev0 = h0;
            hprev1 = h1v;
            float* f = reinterpret_cast<float*>(sh_h);
            int base = 4 * (j >> 1) + (j & 1);
            f[base] = h0;
            f[base + 2] = h1v;

            if (out_all) {
                out_all[((size_t)s0 * TT + t) * HH + j] = h0;
                out_all[((size_t)s1 * TT + t) * HH + j] = h1v;
            }
            if (out_last && t == TT - 1) {
                out_last[s0 * HH + j] = h0;
                out_last[s1 * HH + j] = h1v;
            }
        }
        cur0 = nxt0;
        cur1 = nxt1;
        __syncthreads();
    }
}

// ---------------- FC head: out[b,o] = relu(h_last[b,:]) . fc_w[o,:] + fc_b[o] ----------------
__global__ __launch_bounds__(32) void fc_kernel(
    const float* __restrict__ hlast,  // [B,128]
    const float* __restrict__ fw,     // [3,128]
    const float* __restrict__ fb,     // [3]
    float* __restrict__ outp)         // [B,3]
{
    const int b = blockIdx.x;
    const int lane = threadIdx.x;
    float hv[4];
#pragma unroll
    for (int i = 0; i < 4; i++) {
        float v = hlast[b * HH + lane + 32 * i];
        hv[i] = v > 0.f ? v : 0.f;
    }
#pragma unroll
    for (int o = 0; o < 3; o++) {
        float acc = 0.f;
#pragma unroll
        for (int i = 0; i < 4; i++) acc += hv[i] * fw[o * HH + lane + 32 * i];
#pragma unroll
        for (int d = 16; d; d >>= 1) acc += __shfl_xor_sync(0xffffffffu, acc, d);
        if (lane == 0) outp[b * 3 + o] = acc + fb[o];
    }
}

// ---------------- launch ----------------
extern "C" void kernel_launch(void* const* d_in, const int* in_sizes, int n_in,
                              void* d_out, int out_size) {
    const int* x = (const int*)d_in[0];        // [256,512] int32
    const float* emb = (const float*)d_in[1];  // [29275,128]
    const float* W_ih = (const float*)d_in[2]; // [2,384,128]
    const float* W_hh = (const float*)d_in[3]; // [2,384,128]
    const float* b_ih = (const float*)d_in[4]; // [2,384]
    const float* b_hh = (const float*)d_in[5]; // [2,384]
    const float* fc_w = (const float*)d_in[6]; // [3,128]
    const float* fc_b = (const float*)d_in[7]; // [3]
    float* out = (float*)d_out;                // [256,3]

    float *gx, *h1, *hl;
    cudaGetSymbolAddress((void**)&gx, g_gx);
    cudaGetSymbolAddress((void**)&h1, g_h1);
    cudaGetSymbolAddress((void**)&hl, g_hlast);

    dim3 gg(MM / 64, G3 / 64);

    // Layer 1
    gx_kernel<true><<<gg, 256>>>(x, emb, nullptr, W_ih, b_ih, gx);
    gru_rec_kernel<<<BB / 2, 384>>>(gx, W_hh, b_hh, h1, nullptr);
    // Layer 2
    gx_kernel<false><<<gg, 256>>>(nullptr, nullptr, h1, W_ih + G3 * HH, b_ih + G3, gx);
    gru_rec_kernel<<<BB / 2, 384>>>(gx, W_hh + G3 * HH, b_hh + G3, nullptr, hl);
    // Head
    fc_kernel<<<BB, 32>>>(hl, fc_w, fc_b, out);
}